// round 16
// baseline (speedup 1.0000x reference)
#include <cuda_runtime.h>
#include <cuda_fp16.h>
#include <math.h>
#include <stdint.h>

#define E_      32
#define KSEL    4
#define H_      1024
#define IDIM    768
#define T_      4096
#define NGROUP  8
#define TOPKG   4
#define CAP     1024
#define NASSIGN (T_ * KSEL)

#define YSCALE     0.00390625f
#define YSCALE_INV 256.0f

// ---------------- scratch (device globals; no allocations) ----------------
__device__ __half g_bufh[(size_t)E_ * CAP * H_];
__device__ __half g_acth[(size_t)E_ * CAP * IDIM];
__device__ __half g_w1h[(size_t)E_ * IDIM * H_];
__device__ __half g_w3h[(size_t)E_ * IDIM * H_];
__device__ __half g_w2h[(size_t)E_ * H_ * IDIM];
__device__ __half g_y[(size_t)E_ * CAP * H_];       // y/256 in fp16
__device__ float  g_sc[(size_t)T_ * E_];
__device__ int    g_cnt [E_];
__device__ int    g_tok [E_ * CAP];
__device__ int    g_expi[NASSIGN];
__device__ int    g_slot[NASSIGN];
__device__ float  g_gw  [NASSIGN];

// ---------------- helpers ----------------
__device__ __forceinline__ uint32_t smem_u32(const void* p) {
    uint32_t a;
    asm("{ .reg .u64 t; cvta.to.shared.u64 t, %1; cvt.u32.u64 %0, t; }" : "=r"(a) : "l"(p));
    return a;
}
__device__ __forceinline__ void cp16(uint32_t dst, const void* src) {
    asm volatile("cp.async.cg.shared.global [%0], [%1], 16;" :: "r"(dst), "l"(src));
}
__device__ __forceinline__ void cp_commit() { asm volatile("cp.async.commit_group;"); }
__device__ __forceinline__ void cp_wait1()  { asm volatile("cp.async.wait_group 1;"); }
__device__ __forceinline__ void cp_wait2()  { asm volatile("cp.async.wait_group 2;"); }
#define LDSM4(r, a) \
    asm volatile("ldmatrix.sync.aligned.m8n8.x4.shared.b16 {%0,%1,%2,%3}, [%4];" \
        : "=r"((r)[0]), "=r"((r)[1]), "=r"((r)[2]), "=r"((r)[3]) : "r"(a))
__device__ __forceinline__ void mma_f16(float* c, const uint32_t* a, uint32_t b0, uint32_t b1) {
    asm volatile(
        "mma.sync.aligned.m16n8k16.row.col.f32.f16.f16.f32 "
        "{%0,%1,%2,%3}, {%4,%5,%6,%7}, {%8,%9}, {%0,%1,%2,%3};"
        : "+f"(c[0]), "+f"(c[1]), "+f"(c[2]), "+f"(c[3])
        : "r"(a[0]), "r"(a[1]), "r"(a[2]), "r"(a[3]), "r"(b0), "r"(b1));
}
__device__ __forceinline__ uint32_t pack_h2(float x, float y) {
    __half2 h = __floats2half2_rn(x, y);
    return *(uint32_t*)&h;
}
__device__ __forceinline__ uint32_t swz(uint32_t base, int row, int chunk) {
    return base + (uint32_t)row * 128u + ((uint32_t)(chunk ^ (row & 7)) << 4);
}

// ---------------- merged kernel: score (blocks 0..255) + weight cvt (blocks 256+) ----
#define RTOK 16
#define SCORE_BLKS (T_ / RTOK)
#define CVT_BLKS   2048
__global__ __launch_bounds__(256) void cvt_score(
    const float* __restrict__ x, const float* __restrict__ gate_w,
    const float4* __restrict__ w1, const float4* __restrict__ w3,
    const float4* __restrict__ w2,
    uint2* __restrict__ o1, uint2* __restrict__ o3, uint2* __restrict__ o2, int n4) {
    int tid = threadIdx.x;
    if (blockIdx.x < SCORE_BLKS) {
        extern __shared__ float xs[];
        int lane = tid & 31, w = tid >> 5;
        int tb = blockIdx.x * RTOK;
        const float4* xg = (const float4*)(x + (size_t)tb * H_);
        float4* xs4 = (float4*)xs;
        #pragma unroll
        for (int i = 0; i < RTOK * (H_ / 4) / 256; i++) xs4[tid + i * 256] = xg[tid + i * 256];
        __syncthreads();
        #pragma unroll
        for (int j = 0; j < 4; j++) {
            int e = w * 4 + j;
            const float4* g4 = (const float4*)(gate_w + (size_t)e * H_);
            float acc[RTOK];
            #pragma unroll
            for (int t = 0; t < RTOK; t++) acc[t] = 0.f;
            for (int it = 0; it < 8; it++) {
                float4 gv = g4[it * 32 + lane];
                #pragma unroll
                for (int t = 0; t < RTOK; t++) {
                    float4 xv = *(const float4*)&xs[t * H_ + (it * 32 + lane) * 4];
                    acc[t] += gv.x * xv.x + gv.y * xv.y + gv.z * xv.z + gv.w * xv.w;
                }
            }
            #pragma unroll
            for (int t = 0; t < RTOK; t++) {
                float v = acc[t];
                #pragma unroll
                for (int o = 16; o; o >>= 1) v += __shfl_xor_sync(0xffffffffu, v, o);
                if (lane == 0) g_sc[(size_t)(tb + t) * E_ + e] = v;
            }
        }
    } else {
        int b = blockIdx.x - SCORE_BLKS;
        int stride = CVT_BLKS * 256;
        for (int i = b * 256 + tid; i < n4; i += stride) {
            float4 v = w1[i];
            o1[i] = make_uint2(pack_h2(v.x, v.y), pack_h2(v.z, v.w));
        }
        for (int i = b * 256 + tid; i < n4; i += stride) {
            float4 v = w3[i];
            o3[i] = make_uint2(pack_h2(v.x, v.y), pack_h2(v.z, v.w));
        }
        for (int i = b * 256 + tid; i < n4; i += stride) {
            float4 v = w2[i];
            o2[i] = make_uint2(pack_h2(v.x, v.y), pack_h2(v.z, v.w));
        }
    }
}

// ---------------- fused route+slot: each block recomputes routing for its threads'
// tokens (deterministic, redundant across blocks), then single-pass stable scan for
// its own expert. Each assignment's expi/gw/slot written by exactly one block. ----
__global__ __launch_bounds__(1024) void slot_kernel(const float* __restrict__ bias) {
    int e = blockIdx.x, tid = threadIdx.x;
    int lane = tid & 31, warp = tid >> 5;
    __shared__ int wsum[32];

    int t0 = tid * 4;            // 4 tokens per thread; 16 assignments
    int   ex[16];
    float wv[16];
    #pragma unroll
    for (int j = 0; j < 4; j++) {
        int t = t0 + j;
        float s[E_], sfc[E_];
        #pragma unroll
        for (int q = 0; q < E_; q++) {
            float v = g_sc[(size_t)t * E_ + q];
            s[q]   = 1.f / (1.f + expf(-v));
            sfc[q] = s[q] + bias[q];
        }
        float gs[NGROUP];
        #pragma unroll
        for (int g = 0; g < NGROUP; g++) {
            float m1 = -1e30f, m2 = -1e30f;
            #pragma unroll
            for (int q = 0; q < 4; q++) {
                float v = sfc[g * 4 + q];
                if (v > m1) { m2 = m1; m1 = v; }
                else if (v > m2) m2 = v;
            }
            gs[g] = m1 + m2;
        }
        uint32_t gmask = 0;
        #pragma unroll
        for (int it = 0; it < TOPKG; it++) {
            float best = -1e30f; int bi = 0;
            #pragma unroll
            for (int g = 0; g < NGROUP; g++) {
                bool c = !((gmask >> g) & 1u) && gs[g] > best;
                if (c) { best = gs[g]; bi = g; }
            }
            gmask |= 1u << bi;
        }
        uint32_t emask = 0;
        float rsum = 0.f;
        #pragma unroll
        for (int k = 0; k < KSEL; k++) {
            float best = -1e30f, braw = 0.f; int bi = 0;
            #pragma unroll
            for (int q = 0; q < E_; q++) {
                float v = ((gmask >> (q >> 2)) & 1u) ? sfc[q] : 0.f;
                bool c = !((emask >> q) & 1u) && v > best;
                if (c) { best = v; bi = q; braw = s[q]; }
            }
            emask |= 1u << bi;
            ex[j * 4 + k] = bi;
            wv[j * 4 + k] = braw;
        }
        #pragma unroll
        for (int k = 0; k < KSEL; k++) rsum += wv[j * 4 + k];
        float inv = 1.f / rsum;
        #pragma unroll
        for (int k = 0; k < KSEL; k++) wv[j * 4 + k] *= inv;
    }

    int cnt = 0;
    #pragma unroll
    for (int j = 0; j < 16; j++) cnt += (ex[j] == e);

    int inc = cnt;
    #pragma unroll
    for (int o = 1; o < 32; o <<= 1) {
        int n = __shfl_up_sync(0xffffffffu, inc, o);
        if (lane >= o) inc += n;
    }
    if (lane == 31) wsum[warp] = inc;
    __syncthreads();
    if (warp == 0) {
        int v = wsum[lane];
        #pragma unroll
        for (int o = 1; o < 32; o <<= 1) {
            int n = __shfl_up_sync(0xffffffffu, v, o);
            if (lane >= o) v += n;
        }
        wsum[lane] = v;
    }
    __syncthreads();
    int woff  = (warp == 0) ? 0 : wsum[warp - 1];
    int start = woff + inc - cnt;
    #pragma unroll
    for (int j = 0; j < 16; j++) {
        if (ex[j] == e) {
            int a = tid * 16 + j;
            g_expi[a] = e;
            g_gw[a]   = wv[j];
            if (start < CAP) {
                g_slot[a] = start;
                g_tok[e * CAP + start] = a >> 2;
            } else {
                g_slot[a] = -1;
            }
            start++;
        }
    }
    if (tid == 1023) g_cnt[e] = (woff + inc) < CAP ? (woff + inc) : CAP;
}

// gather: token rows -> per-expert fp16 buffers
__global__ void gather_kernel(const float* __restrict__ x) {
    int e = blockIdx.y, slot = blockIdx.x;
    if (slot >= g_cnt[e]) return;
    int t = g_tok[e * CAP + slot];
    const float4* src = (const float4*)(x + (size_t)t * H_);
    uint2* dst = (uint2*)(g_bufh + ((size_t)e * CAP + slot) * H_);
    for (int i = threadIdx.x; i < H_ / 4; i += blockDim.x) {
        float4 v = src[i];
        dst[i] = make_uint2(pack_h2(v.x, v.y), pack_h2(v.z, v.w));
    }
}

// ---------------- GEMM common ----------------
#define PS      16384

// ---------------- GEMM1: h1/h3 fp16 + fused SiLU (BK=64, 4-stage pipeline) ----------------
#define G1_NSTG   4
#define G1_STAGE  (3 * PS)              // 49152
#define G1_SMEM   (G1_NSTG * G1_STAGE)  // 196608

__global__ __launch_bounds__(256) void gemm1_mma(void) {
    int e   = blockIdx.z;
    int cnt = g_cnt[e];
    int m0  = blockIdx.y * 128;
    if (m0 >= cnt) return;
    int n0  = blockIdx.x * 128;

    extern __shared__ char sm[];
    uint32_t sb = smem_u32(sm);
    int tid = threadIdx.x, lane = tid & 31, wid = tid >> 5;
    int wm = (wid & 1) * 64, wn = (wid >> 1) * 32;
    int g = lane >> 2, tg = lane & 3;
    int lane15 = lane & 15;
    int lchunk = lane >> 4;

    const __half* srcs[3] = {
        g_bufh + ((size_t)e * CAP  + m0) * H_,
        g_w1h  + ((size_t)e * IDIM + n0) * H_,
        g_w3h  + ((size_t)e * IDIM + n0) * H_
    };
    int lrow = tid >> 1;
    int half = tid & 1;

    #pragma unroll
    for (int st = 0; st < G1_NSTG - 1; st++) {
        uint32_t s0 = sb + st * G1_STAGE;
        int k0 = st * 64;
        #pragma unroll
        for (int p = 0; p < 3; p++) {
            const __half* gp = srcs[p] + (size_t)lrow * H_ + k0;
            #pragma unroll
            for (int j = 0; j < 4; j++) {
                int ch = half * 4 + j;
                cp16(swz(s0 + p * PS, lrow, ch), gp + ch * 8);
            }
        }
        cp_commit();
    }

    float c1[4][4][4] = {}, c3[4][4][4] = {};

    const int NK = H_ / 64;  // 16
    for (int kt = 0; kt < NK; kt++) {
        cp_wait2();
        __syncthreads();
        if (kt + G1_NSTG - 1 < NK) {
            uint32_t s0 = sb + ((kt + G1_NSTG - 1) % G1_NSTG) * G1_STAGE;
            int k0 = (kt + G1_NSTG - 1) * 64;
            #pragma unroll
            for (int p = 0; p < 3; p++) {
                const __half* gp = srcs[p] + (size_t)lrow * H_ + k0;
                #pragma unroll
                for (int j = 0; j < 4; j++) {
                    int ch = half * 4 + j;
                    cp16(swz(s0 + p * PS, lrow, ch), gp + ch * 8);
                }
            }
        }
        cp_commit();

        uint32_t bs = sb + (kt % G1_NSTG) * G1_STAGE;
        #pragma unroll
        for (int kb = 0; kb < 4; kb++) {
            int ch = kb * 2 + lchunk;
            uint32_t Af[4][4];
            #pragma unroll
            for (int mi = 0; mi < 4; mi++)
                LDSM4(Af[mi], swz(bs, wm + lane15 + mi * 16, ch));
            uint32_t t_[4], Bf[4][2];
            #pragma unroll
            for (int n2 = 0; n2 < 2; n2++) {
                LDSM4(t_, swz(bs + PS, wn + lane15 + n2 * 16, ch));
                Bf[2 * n2][0] = t_[0]; Bf[2 * n2][1] = t_[2];
                Bf[2 * n2 + 1][0] = t_[1]; Bf[2 * n2 + 1][1] = t_[3];
            }
            #pragma unroll
            for (int mi = 0; mi < 4; mi++)
                #pragma unroll
                for (int ni = 0; ni < 4; ni++)
                    mma_f16(c1[mi][ni], Af[mi], Bf[ni][0], Bf[ni][1]);
            #pragma unroll
            for (int n2 = 0; n2 < 2; n2++) {
                LDSM4(t_, swz(bs + 2 * PS, wn + lane15 + n2 * 16, ch));
                Bf[2 * n2][0] = t_[0]; Bf[2 * n2][1] = t_[2];
                Bf[2 * n2 + 1][0] = t_[1]; Bf[2 * n2 + 1][1] = t_[3];
            }
            #pragma unroll
            for (int mi = 0; mi < 4; mi++)
                #pragma unroll
                for (int ni = 0; ni < 4; ni++)
                    mma_f16(c3[mi][ni], Af[mi], Bf[ni][0], Bf[ni][1]);
        }
    }

    #pragma unroll
    for (int mi = 0; mi < 4; mi++) {
        int r0 = m0 + wm + mi * 16 + g;
        #pragma unroll
        for (int ni = 0; ni < 4; ni++) {
            int cb = n0 + wn + ni * 8 + tg * 2;
            float h1a = c1[mi][ni][0], h1b = c1[mi][ni][1];
            float v0 = h1a / (1.f + expf(-h1a)) * c3[mi][ni][0];
            float v1 = h1b / (1.f + expf(-h1b)) * c3[mi][ni][1];
            float h1c = c1[mi][ni][2], h1d = c1[mi][ni][3];
            float v2 = h1c / (1.f + expf(-h1c)) * c3[mi][ni][2];
            float v3 = h1d / (1.f + expf(-h1d)) * c3[mi][ni][3];
            size_t o0 = ((size_t)e * CAP + r0) * IDIM + cb;
            *(uint32_t*)(g_acth + o0) = pack_h2(v0, v1);
            size_t o1 = ((size_t)e * CAP + r0 + 8) * IDIM + cb;
            *(uint32_t*)(g_acth + o1) = pack_h2(v2, v3);
        }
    }
}

// ---------------- GEMM2: y = act @ w2^T (BK=64, 2 CTAs/SM), scaled fp16 output ----------------
#define G2_NSTG   3
#define G2_STAGE  (2 * PS)
#define G2_SMEM   (G2_NSTG * G2_STAGE)

__global__ __launch_bounds__(256, 2) void gemm2_mma(void) {
    int e   = blockIdx.z;
    int cnt = g_cnt[e];
    int m0  = blockIdx.y * 128;
    if (m0 >= cnt) return;
    int n0  = blockIdx.x * 128;

    extern __shared__ char sm[];
    uint32_t sb = smem_u32(sm);
    int tid = threadIdx.x, lane = tid & 31, wid = tid >> 5;
    int wm = (wid & 1) * 64, wn = (wid >> 1) * 32;
    int g = lane >> 2, tg = lane & 3;
    int lane15 = lane & 15;
    int lchunk = lane >> 4;

    const __half* srcs[2] = {
        g_acth + ((size_t)e * CAP + m0) * IDIM,
        g_w2h  + ((size_t)e * H_  + n0) * IDIM
    };
    int lrow = tid >> 1;
    int half = tid & 1;

    #pragma unroll
    for (int st = 0; st < G2_NSTG - 1; st++) {
        uint32_t s0 = sb + st * G2_STAGE;
        int k0 = st * 64;
        #pragma unroll
        for (int p = 0; p < 2; p++) {
            const __half* gp = srcs[p] + (size_t)lrow * IDIM + k0;
            #pragma unroll
            for (int j = 0; j < 4; j++) {
                int ch = half * 4 + j;
                cp16(swz(s0 + p * PS, lrow, ch), gp + ch * 8);
            }
        }
        cp_commit();
    }

    float cc[4][4][4] = {};

    const int NK = IDIM / 64;
    for (int kt = 0; kt < NK; kt++) {
        cp_wait1();
        __syncthreads();
        if (kt + G2_NSTG - 1 < NK) {
            uint32_t s0 = sb + ((kt + G2_NSTG - 1) % G2_NSTG) * G2_STAGE;
            int k0 = (kt + G2_NSTG - 1) * 64;
            #pragma unroll
            for (int p = 0; p < 2; p++) {
                const __half* gp = srcs[p] + (size_t)lrow * IDIM + k0;
                #pragma unroll
                for (int j = 0; j < 4; j++) {
                    int ch = half * 4 + j;
                    cp16(swz(s0 + p * PS, lrow, ch), gp + ch * 8);
                }
            }
        }
        cp_commit();

        uint32_t bs = sb + (kt % G2_NSTG) * G2_STAGE;
        #pragma unroll
        for (int kb = 0; kb < 4; kb++) {
            int ch = kb * 2 + lchunk;
            uint32_t Af[4][4];
            #pragma unroll
            for (int mi = 0; mi < 4; mi++)
                LDSM4(Af[mi], swz(bs, wm + lane15 + mi * 16, ch));
            uint32_t t_[4], Bf[4][2];
            #pragma unroll
            for (int n2 = 0; n2 < 2; n2++) {
                LDSM4(t_, swz(bs + PS, wn + lane15 + n2 * 16, ch));
                Bf[2 * n2][0] = t_[0]; Bf[2 * n2][1] = t_[2];
                Bf[2 * n2 + 1][0] = t_[1]; Bf[2 * n2 + 1][1] = t_[3];
            }
            #pragma unroll
            for (int mi = 0; mi < 4; mi++)
                #pragma unroll
                for (int ni = 0; ni < 4; ni++)
                    mma_f16(cc[mi][ni], Af[mi], Bf[ni][0], Bf[ni][1]);
        }
    }

    #pragma unroll
    for (int mi = 0; mi < 4; mi++) {
        int r0 = m0 + wm + mi * 16 + g;
        #pragma unroll
        for (int ni = 0; ni < 4; ni++) {
            int cb = n0 + wn + ni * 8 + tg * 2;
            *(uint32_t*)(g_y + ((size_t)e * CAP + r0) * H_ + cb) =
                pack_h2(cc[mi][ni][0] * YSCALE, cc[mi][ni][1] * YSCALE);
            *(uint32_t*)(g_y + ((size_t)e * CAP + r0 + 8) * H_ + cb) =
                pack_h2(cc[mi][ni][2] * YSCALE, cc[mi][ni][3] * YSCALE);
        }
    }
}

// ---------------- combine: scaled-fp16 y -> fp32 out ----------------
__global__ void combine_kernel(float* __restrict__ out) {
    int t = blockIdx.x;
    int i = threadIdx.x;
    float4 acc = make_float4(0.f, 0.f, 0.f, 0.f);
    #pragma unroll
    for (int k = 0; k < KSEL; k++) {
        int a = t * KSEL + k;
        int slot = g_slot[a];
        if (slot < 0) continue;
        int e = g_expi[a];
        float w = g_gw[a] * YSCALE_INV;
        const uint2* yr = (const uint2*)(g_y + ((size_t)e * CAP + slot) * H_);
        uint2 v = yr[i];
        float2 f01 = __half22float2(*(__half2*)&v.x);
        float2 f23 = __half22float2(*(__half2*)&v.y);
        acc.x += w * f01.x; acc.y += w * f01.y;
        acc.z += w * f23.x; acc.w += w * f23.y;
    }
    ((float4*)(out + (size_t)t * H_))[i] = acc;
}

// ---------------- launch ----------------
extern "C" void kernel_launch(void* const* d_in, const int* in_sizes, int n_in,
                              void* d_out, int out_size) {
    (void)in_sizes; (void)n_in; (void)out_size;
    const float* x      = (const float*)d_in[0];
    const float* gate_w = (const float*)d_in[1];
    const float* w1     = (const float*)d_in[2];
    const float* w3     = (const float*)d_in[3];
    const float* w2     = (const float*)d_in[4];
    const float* bias   = (const float*)d_in[5];
    float*       out    = (float*)d_out;

    const int RSMEM = RTOK * H_ * 4;
    cudaFuncSetAttribute(cvt_score, cudaFuncAttributeMaxDynamicSharedMemorySize, RSMEM);
    cudaFuncSetAttribute(gemm1_mma, cudaFuncAttributeMaxDynamicSharedMemorySize, G1_SMEM);
    cudaFuncSetAttribute(gemm2_mma, cudaFuncAttributeMaxDynamicSharedMemorySize, G2_SMEM);

    void *p_w1h, *p_w3h, *p_w2h;
    cudaGetSymbolAddress(&p_w1h, g_w1h);
    cudaGetSymbolAddress(&p_w3h, g_w3h);
    cudaGetSymbolAddress(&p_w2h, g_w2h);

    const int n4 = E_ * IDIM * H_ / 4;
    cvt_score<<<SCORE_BLKS + CVT_BLKS, 256, RSMEM>>>(
        x, gate_w, (const float4*)w1, (const float4*)w3, (const float4*)w2,
        (uint2*)p_w1h, (uint2*)p_w3h, (uint2*)p_w2h, n4);

    slot_kernel<<<E_, 1024>>>(bias);   // fused route+slot
    gather_kernel<<<dim3(CAP, E_), 256>>>(x);
    gemm1_mma<<<dim3(IDIM / 128, CAP / 128, E_), 256, G1_SMEM>>>();
    gemm2_mma<<<dim3(H_ / 128, CAP / 128, E_), 256, G2_SMEM>>>();
    combine_kernel<<<T_, 256>>>(out);
}

// round 17
// speedup vs baseline: 1.2825x; 1.2825x over previous
#include <cuda_runtime.h>
#include <cuda_fp16.h>
#include <math.h>
#include <stdint.h>

#define E_      32
#define KSEL    4
#define H_      1024
#define IDIM    768
#define T_      4096
#define NGROUP  8
#define TOPKG   4
#define CAP     1024
#define NASSIGN (T_ * KSEL)

#define YSCALE     0.00390625f
#define YSCALE_INV 256.0f

// ---------------- scratch (device globals; no allocations) ----------------
__device__ __half g_bufh[(size_t)E_ * CAP * H_];
__device__ __half g_acth[(size_t)E_ * CAP * IDIM];
__device__ __half g_w1h[(size_t)E_ * IDIM * H_];
__device__ __half g_w3h[(size_t)E_ * IDIM * H_];
__device__ __half g_w2h[(size_t)E_ * H_ * IDIM];
__device__ __half g_y[(size_t)E_ * CAP * H_];       // y/256 in fp16
__device__ float  g_sc[(size_t)T_ * E_];
__device__ int    g_cnt [E_];
__device__ int    g_tok [E_ * CAP];
__device__ int    g_expi[NASSIGN];
__device__ int    g_slot[NASSIGN];
__device__ float  g_gw  [NASSIGN];

// ---------------- helpers ----------------
__device__ __forceinline__ uint32_t smem_u32(const void* p) {
    uint32_t a;
    asm("{ .reg .u64 t; cvta.to.shared.u64 t, %1; cvt.u32.u64 %0, t; }" : "=r"(a) : "l"(p));
    return a;
}
__device__ __forceinline__ void cp16(uint32_t dst, const void* src) {
    asm volatile("cp.async.cg.shared.global [%0], [%1], 16;" :: "r"(dst), "l"(src));
}
__device__ __forceinline__ void cp_commit() { asm volatile("cp.async.commit_group;"); }
__device__ __forceinline__ void cp_wait1()  { asm volatile("cp.async.wait_group 1;"); }
#define LDSM4(r, a) \
    asm volatile("ldmatrix.sync.aligned.m8n8.x4.shared.b16 {%0,%1,%2,%3}, [%4];" \
        : "=r"((r)[0]), "=r"((r)[1]), "=r"((r)[2]), "=r"((r)[3]) : "r"(a))
__device__ __forceinline__ void mma_f16(float* c, const uint32_t* a, uint32_t b0, uint32_t b1) {
    asm volatile(
        "mma.sync.aligned.m16n8k16.row.col.f32.f16.f16.f32 "
        "{%0,%1,%2,%3}, {%4,%5,%6,%7}, {%8,%9}, {%0,%1,%2,%3};"
        : "+f"(c[0]), "+f"(c[1]), "+f"(c[2]), "+f"(c[3])
        : "r"(a[0]), "r"(a[1]), "r"(a[2]), "r"(a[3]), "r"(b0), "r"(b1));
}
__device__ __forceinline__ uint32_t pack_h2(float x, float y) {
    __half2 h = __floats2half2_rn(x, y);
    return *(uint32_t*)&h;
}
__device__ __forceinline__ uint32_t swz(uint32_t base, int row, int chunk) {
    return base + (uint32_t)row * 128u + ((uint32_t)(chunk ^ (row & 7)) << 4);
}

// ---------------- merged kernel: score (blocks 0..255) + weight cvt (blocks 256+) ----
#define RTOK 16
#define SCORE_BLKS (T_ / RTOK)
#define CVT_BLKS   2048
__global__ __launch_bounds__(256) void cvt_score(
    const float* __restrict__ x, const float* __restrict__ gate_w,
    const float4* __restrict__ w1, const float4* __restrict__ w3,
    const float4* __restrict__ w2,
    uint2* __restrict__ o1, uint2* __restrict__ o3, uint2* __restrict__ o2, int n4) {
    int tid = threadIdx.x;
    if (blockIdx.x < SCORE_BLKS) {
        extern __shared__ float xs[];
        int lane = tid & 31, w = tid >> 5;
        int tb = blockIdx.x * RTOK;
        const float4* xg = (const float4*)(x + (size_t)tb * H_);
        float4* xs4 = (float4*)xs;
        #pragma unroll
        for (int i = 0; i < RTOK * (H_ / 4) / 256; i++) xs4[tid + i * 256] = xg[tid + i * 256];
        __syncthreads();
        #pragma unroll
        for (int j = 0; j < 4; j++) {
            int e = w * 4 + j;
            const float4* g4 = (const float4*)(gate_w + (size_t)e * H_);
            float acc[RTOK];
            #pragma unroll
            for (int t = 0; t < RTOK; t++) acc[t] = 0.f;
            for (int it = 0; it < 8; it++) {
                float4 gv = g4[it * 32 + lane];
                #pragma unroll
                for (int t = 0; t < RTOK; t++) {
                    float4 xv = *(const float4*)&xs[t * H_ + (it * 32 + lane) * 4];
                    acc[t] += gv.x * xv.x + gv.y * xv.y + gv.z * xv.z + gv.w * xv.w;
                }
            }
            #pragma unroll
            for (int t = 0; t < RTOK; t++) {
                float v = acc[t];
                #pragma unroll
                for (int o = 16; o; o >>= 1) v += __shfl_xor_sync(0xffffffffu, v, o);
                if (lane == 0) g_sc[(size_t)(tb + t) * E_ + e] = v;
            }
        }
    } else {
        int b = blockIdx.x - SCORE_BLKS;
        int stride = CVT_BLKS * 256;
        for (int i = b * 256 + tid; i < n4; i += stride) {
            float4 v = w1[i];
            o1[i] = make_uint2(pack_h2(v.x, v.y), pack_h2(v.z, v.w));
        }
        for (int i = b * 256 + tid; i < n4; i += stride) {
            float4 v = w3[i];
            o3[i] = make_uint2(pack_h2(v.x, v.y), pack_h2(v.z, v.w));
        }
        for (int i = b * 256 + tid; i < n4; i += stride) {
            float4 v = w2[i];
            o2[i] = make_uint2(pack_h2(v.x, v.y), pack_h2(v.z, v.w));
        }
    }
}

// ---------------- router stage 2: top-k, register-only bitmask selection ----------------
__global__ __launch_bounds__(256) void route_kernel(const float* __restrict__ bias) {
    int t = blockIdx.x * blockDim.x + threadIdx.x;
    if (t >= T_) return;

    float s[E_], sfc[E_];
    #pragma unroll
    for (int e = 0; e < E_; e++) {
        float v = g_sc[(size_t)t * E_ + e];
        s[e]   = 1.f / (1.f + expf(-v));
        sfc[e] = s[e] + bias[e];
    }
    float gs[NGROUP];
    #pragma unroll
    for (int g = 0; g < NGROUP; g++) {
        float m1 = -1e30f, m2 = -1e30f;
        #pragma unroll
        for (int j = 0; j < 4; j++) {
            float v = sfc[g * 4 + j];
            if (v > m1) { m2 = m1; m1 = v; }
            else if (v > m2) m2 = v;
        }
        gs[g] = m1 + m2;
    }
    uint32_t gmask = 0;
    #pragma unroll
    for (int it = 0; it < TOPKG; it++) {
        float best = -1e30f; int bi = 0;
        #pragma unroll
        for (int g = 0; g < NGROUP; g++) {
            bool c = !((gmask >> g) & 1u) && gs[g] > best;
            if (c) { best = gs[g]; bi = g; }
        }
        gmask |= 1u << bi;
    }
    uint32_t emask = 0;
    int   sel[KSEL];
    float rw[KSEL];
    #pragma unroll
    for (int k = 0; k < KSEL; k++) {
        float best = -1e30f, braw = 0.f; int bi = 0;
        #pragma unroll
        for (int e = 0; e < E_; e++) {
            float v = ((gmask >> (e >> 2)) & 1u) ? sfc[e] : 0.f;
            bool c = !((emask >> e) & 1u) && v > best;
            if (c) { best = v; bi = e; braw = s[e]; }
        }
        emask |= 1u << bi;
        sel[k] = bi;
        rw[k]  = braw;
    }
    float inv = 1.f / (rw[0] + rw[1] + rw[2] + rw[3]);
    #pragma unroll
    for (int k = 0; k < KSEL; k++) {
        int a = t * KSEL + k;
        g_expi[a] = sel[k];
        g_gw[a]   = rw[k] * inv;
    }
}

// ---------------- slot: single-pass scan ----------------
__global__ __launch_bounds__(1024) void slot_kernel() {
    int e = blockIdx.x, tid = threadIdx.x;
    int lane = tid & 31, warp = tid >> 5;
    __shared__ int wsum[32];

    int a0 = tid * 16;
    int ex[16];
    int cnt = 0;
    #pragma unroll
    for (int j = 0; j < 16; j++) {
        ex[j] = g_expi[a0 + j];
        cnt += (ex[j] == e);
    }
    int inc = cnt;
    #pragma unroll
    for (int o = 1; o < 32; o <<= 1) {
        int n = __shfl_up_sync(0xffffffffu, inc, o);
        if (lane >= o) inc += n;
    }
    if (lane == 31) wsum[warp] = inc;
    __syncthreads();
    if (warp == 0) {
        int v = wsum[lane];
        #pragma unroll
        for (int o = 1; o < 32; o <<= 1) {
            int n = __shfl_up_sync(0xffffffffu, v, o);
            if (lane >= o) v += n;
        }
        wsum[lane] = v;
    }
    __syncthreads();
    int woff  = (warp == 0) ? 0 : wsum[warp - 1];
    int start = woff + inc - cnt;
    #pragma unroll
    for (int j = 0; j < 16; j++) {
        if (ex[j] == e) {
            int a = a0 + j;
            if (start < CAP) {
                g_slot[a] = start;
                g_tok[e * CAP + start] = a >> 2;
            } else {
                g_slot[a] = -1;
            }
            start++;
        }
    }
    if (tid == 1023) g_cnt[e] = (woff + inc) < CAP ? (woff + inc) : CAP;
}

// gather: token rows -> per-expert fp16 buffers
__global__ void gather_kernel(const float* __restrict__ x) {
    int e = blockIdx.y, slot = blockIdx.x;
    if (slot >= g_cnt[e]) return;
    int t = g_tok[e * CAP + slot];
    const float4* src = (const float4*)(x + (size_t)t * H_);
    uint2* dst = (uint2*)(g_bufh + ((size_t)e * CAP + slot) * H_);
    for (int i = threadIdx.x; i < H_ / 4; i += blockDim.x) {
        float4 v = src[i];
        dst[i] = make_uint2(pack_h2(v.x, v.y), pack_h2(v.z, v.w));
    }
}

// ---------------- GEMM common ----------------
#define PS      16384
#define NSTG    3

// ---------------- GEMM1: 512 threads (16 warps), warp tile 64x16, BK=64 ----------------
#define G1_STAGE  (3 * PS)           // 49152
#define G1_SMEM   (NSTG * G1_STAGE)  // 147456

__global__ __launch_bounds__(512) void gemm1_mma(void) {
    int e   = blockIdx.z;
    int cnt = g_cnt[e];
    int m0  = blockIdx.y * 128;
    if (m0 >= cnt) return;
    int n0  = blockIdx.x * 128;

    extern __shared__ char sm[];
    uint32_t sb = smem_u32(sm);
    int tid = threadIdx.x, lane = tid & 31, wid = tid >> 5;
    int wm = (wid & 1) * 64, wn = (wid >> 1) * 16;   // 2 x 8 warp grid
    int g = lane >> 2, tg = lane & 3;
    int lane15 = lane & 15;
    int lchunk = lane >> 4;

    const __half* srcs[3] = {
        g_bufh + ((size_t)e * CAP  + m0) * H_,
        g_w1h  + ((size_t)e * IDIM + n0) * H_,
        g_w3h  + ((size_t)e * IDIM + n0) * H_
    };
    int lrow = tid >> 2;        // 0..127 (4 threads per row)
    int lq   = tid & 3;         // quarter: 2 chunks each

    #pragma unroll
    for (int st = 0; st < NSTG - 1; st++) {
        uint32_t s0 = sb + st * G1_STAGE;
        int k0 = st * 64;
        #pragma unroll
        for (int p = 0; p < 3; p++) {
            const __half* gp = srcs[p] + (size_t)lrow * H_ + k0;
            #pragma unroll
            for (int j = 0; j < 2; j++) {
                int ch = lq * 2 + j;
                cp16(swz(s0 + p * PS, lrow, ch), gp + ch * 8);
            }
        }
        cp_commit();
    }

    float c1[4][2][4] = {}, c3[4][2][4] = {};

    const int NK = H_ / 64;  // 16
    for (int kt = 0; kt < NK; kt++) {
        cp_wait1();
        __syncthreads();
        if (kt + NSTG - 1 < NK) {
            uint32_t s0 = sb + ((kt + NSTG - 1) % NSTG) * G1_STAGE;
            int k0 = (kt + NSTG - 1) * 64;
            #pragma unroll
            for (int p = 0; p < 3; p++) {
                const __half* gp = srcs[p] + (size_t)lrow * H_ + k0;
                #pragma unroll
                for (int j = 0; j < 2; j++) {
                    int ch = lq * 2 + j;
                    cp16(swz(s0 + p * PS, lrow, ch), gp + ch * 8);
                }
            }
        }
        cp_commit();

        uint32_t bs = sb + (kt % NSTG) * G1_STAGE;
        #pragma unroll
        for (int kb = 0; kb < 4; kb++) {
            int ch = kb * 2 + lchunk;
            uint32_t Af[4][4];
            #pragma unroll
            for (int mi = 0; mi < 4; mi++)
                LDSM4(Af[mi], swz(bs, wm + lane15 + mi * 16, ch));
            uint32_t t_[4], Bf[2][2];
            // B1 (16 rows -> ni=0,1)
            LDSM4(t_, swz(bs + PS, wn + lane15, ch));
            Bf[0][0] = t_[0]; Bf[0][1] = t_[2];
            Bf[1][0] = t_[1]; Bf[1][1] = t_[3];
            #pragma unroll
            for (int mi = 0; mi < 4; mi++)
                #pragma unroll
                for (int ni = 0; ni < 2; ni++)
                    mma_f16(c1[mi][ni], Af[mi], Bf[ni][0], Bf[ni][1]);
            // B3
            LDSM4(t_, swz(bs + 2 * PS, wn + lane15, ch));
            Bf[0][0] = t_[0]; Bf[0][1] = t_[2];
            Bf[1][0] = t_[1]; Bf[1][1] = t_[3];
            #pragma unroll
            for (int mi = 0; mi < 4; mi++)
                #pragma unroll
                for (int ni = 0; ni < 2; ni++)
                    mma_f16(c3[mi][ni], Af[mi], Bf[ni][0], Bf[ni][1]);
        }
    }

    // epilogue: act = silu(h1)*h3 -> fp16
    #pragma unroll
    for (int mi = 0; mi < 4; mi++) {
        int r0 = m0 + wm + mi * 16 + g;
        #pragma unroll
        for (int ni = 0; ni < 2; ni++) {
            int cb = n0 + wn + ni * 8 + tg * 2;
            float h1a = c1[mi][ni][0], h1b = c1[mi][ni][1];
            float v0 = h1a / (1.f + expf(-h1a)) * c3[mi][ni][0];
            float v1 = h1b / (1.f + expf(-h1b)) * c3[mi][ni][1];
            float h1c = c1[mi][ni][2], h1d = c1[mi][ni][3];
            float v2 = h1c / (1.f + expf(-h1c)) * c3[mi][ni][2];
            float v3 = h1d / (1.f + expf(-h1d)) * c3[mi][ni][3];
            size_t o0 = ((size_t)e * CAP + r0) * IDIM + cb;
            *(uint32_t*)(g_acth + o0) = pack_h2(v0, v1);
            size_t o1 = ((size_t)e * CAP + r0 + 8) * IDIM + cb;
            *(uint32_t*)(g_acth + o1) = pack_h2(v2, v3);
        }
    }
}

// ---------------- GEMM2: y = act @ w2^T (BK=64, 2 CTAs/SM), scaled fp16 output ----------------
#define G2_STAGE  (2 * PS)
#define G2_SMEM   (NSTG * G2_STAGE)

__global__ __launch_bounds__(256, 2) void gemm2_mma(void) {
    int e   = blockIdx.z;
    int cnt = g_cnt[e];
    int m0  = blockIdx.y * 128;
    if (m0 >= cnt) return;
    int n0  = blockIdx.x * 128;

    extern __shared__ char sm[];
    uint32_t sb = smem_u32(sm);
    int tid = threadIdx.x, lane = tid & 31, wid = tid >> 5;
    int wm = (wid & 1) * 64, wn = (wid >> 1) * 32;
    int g = lane >> 2, tg = lane & 3;
    int lane15 = lane & 15;
    int lchunk = lane >> 4;

    const __half* srcs[2] = {
        g_acth + ((size_t)e * CAP + m0) * IDIM,
        g_w2h  + ((size_t)e * H_  + n0) * IDIM
    };
    int lrow = tid >> 1;
    int half = tid & 1;

    #pragma unroll
    for (int st = 0; st < NSTG - 1; st++) {
        uint32_t s0 = sb + st * G2_STAGE;
        int k0 = st * 64;
        #pragma unroll
        for (int p = 0; p < 2; p++) {
            const __half* gp = srcs[p] + (size_t)lrow * IDIM + k0;
            #pragma unroll
            for (int j = 0; j < 4; j++) {
                int ch = half * 4 + j;
                cp16(swz(s0 + p * PS, lrow, ch), gp + ch * 8);
            }
        }
        cp_commit();
    }

    float cc[4][4][4] = {};

    const int NK = IDIM / 64;
    for (int kt = 0; kt < NK; kt++) {
        cp_wait1();
        __syncthreads();
        if (kt + NSTG - 1 < NK) {
            uint32_t s0 = sb + ((kt + NSTG - 1) % NSTG) * G2_STAGE;
            int k0 = (kt + NSTG - 1) * 64;
            #pragma unroll
            for (int p = 0; p < 2; p++) {
                const __half* gp = srcs[p] + (size_t)lrow * IDIM + k0;
                #pragma unroll
                for (int j = 0; j < 4; j++) {
                    int ch = half * 4 + j;
                    cp16(swz(s0 + p * PS, lrow, ch), gp + ch * 8);
                }
            }
        }
        cp_commit();

        uint32_t bs = sb + (kt % NSTG) * G2_STAGE;
        #pragma unroll
        for (int kb = 0; kb < 4; kb++) {
            int ch = kb * 2 + lchunk;
            uint32_t Af[4][4];
            #pragma unroll
            for (int mi = 0; mi < 4; mi++)
                LDSM4(Af[mi], swz(bs, wm + lane15 + mi * 16, ch));
            uint32_t t_[4], Bf[4][2];
            #pragma unroll
            for (int n2 = 0; n2 < 2; n2++) {
                LDSM4(t_, swz(bs + PS, wn + lane15 + n2 * 16, ch));
                Bf[2 * n2][0] = t_[0]; Bf[2 * n2][1] = t_[2];
                Bf[2 * n2 + 1][0] = t_[1]; Bf[2 * n2 + 1][1] = t_[3];
            }
            #pragma unroll
            for (int mi = 0; mi < 4; mi++)
                #pragma unroll
                for (int ni = 0; ni < 4; ni++)
                    mma_f16(cc[mi][ni], Af[mi], Bf[ni][0], Bf[ni][1]);
        }
    }

    #pragma unroll
    for (int mi = 0; mi < 4; mi++) {
        int r0 = m0 + wm + mi * 16 + g;
        #pragma unroll
        for (int ni = 0; ni < 4; ni++) {
            int cb = n0 + wn + ni * 8 + tg * 2;
            *(uint32_t*)(g_y + ((size_t)e * CAP + r0) * H_ + cb) =
                pack_h2(cc[mi][ni][0] * YSCALE, cc[mi][ni][1] * YSCALE);
            *(uint32_t*)(g_y + ((size_t)e * CAP + r0 + 8) * H_ + cb) =
                pack_h2(cc[mi][ni][2] * YSCALE, cc[mi][ni][3] * YSCALE);
        }
    }
}

// ---------------- combine: scaled-fp16 y -> fp32 out ----------------
__global__ void combine_kernel(float* __restrict__ out) {
    int t = blockIdx.x;
    int i = threadIdx.x;
    float4 acc = make_float4(0.f, 0.f, 0.f, 0.f);
    #pragma unroll
    for (int k = 0; k < KSEL; k++) {
        int a = t * KSEL + k;
        int slot = g_slot[a];
        if (slot < 0) continue;
        int e = g_expi[a];
        float w = g_gw[a] * YSCALE_INV;
        const uint2* yr = (const uint2*)(g_y + ((size_t)e * CAP + slot) * H_);
        uint2 v = yr[i];
        float2 f01 = __half22float2(*(__half2*)&v.x);
        float2 f23 = __half22float2(*(__half2*)&v.y);
        acc.x += w * f01.x; acc.y += w * f01.y;
        acc.z += w * f23.x; acc.w += w * f23.y;
    }
    ((float4*)(out + (size_t)t * H_))[i] = acc;
}

// ---------------- launch ----------------
extern "C" void kernel_launch(void* const* d_in, const int* in_sizes, int n_in,
                              void* d_out, int out_size) {
    (void)in_sizes; (void)n_in; (void)out_size;
    const float* x      = (const float*)d_in[0];
    const float* gate_w = (const float*)d_in[1];
    const float* w1     = (const float*)d_in[2];
    const float* w3     = (const float*)d_in[3];
    const float* w2     = (const float*)d_in[4];
    const float* bias   = (const float*)d_in[5];
    float*       out    = (float*)d_out;

    const int RSMEM = RTOK * H_ * 4;
    cudaFuncSetAttribute(cvt_score, cudaFuncAttributeMaxDynamicSharedMemorySize, RSMEM);
    cudaFuncSetAttribute(gemm1_mma, cudaFuncAttributeMaxDynamicSharedMemorySize, G1_SMEM);
    cudaFuncSetAttribute(gemm2_mma, cudaFuncAttributeMaxDynamicSharedMemorySize, G2_SMEM);

    void *p_w1h, *p_w3h, *p_w2h;
    cudaGetSymbolAddress(&p_w1h, g_w1h);
    cudaGetSymbolAddress(&p_w3h, g_w3h);
    cudaGetSymbolAddress(&p_w2h, g_w2h);

    const int n4 = E_ * IDIM * H_ / 4;
    cvt_score<<<SCORE_BLKS + CVT_BLKS, 256, RSMEM>>>(
        x, gate_w, (const float4*)w1, (const float4*)w3, (const float4*)w2,
        (uint2*)p_w1h, (uint2*)p_w3h, (uint2*)p_w2h, n4);

    route_kernel<<<T_ / 256, 256>>>(bias);
    slot_kernel<<<E_, 1024>>>();
    gather_kernel<<<dim3(CAP, E_), 256>>>(x);
    gemm1_mma<<<dim3(IDIM / 128, CAP / 128, E_), 512, G1_SMEM>>>();
    gemm2_mma<<<dim3(H_ / 128, CAP / 128, E_), 256, G2_SMEM>>>();
    combine_kernel<<<T_, 256>>>(out);
}